// round 9
// baseline (speedup 1.0000x reference)
#include <cuda_runtime.h>
#include <stdint.h>

// Shapes (fixed):
//   x:        (B, M, N)  float32          B=32, M=512, N=128
//   location: (B, M, 2)  int64/int32 (y, x), H=W=128
//   out:      (B, N, H, W) float32
#define BB   32
#define MM   512
#define NN   128
#define WPX  128
#define HWPX 16384   // 128*128
#define HW4  4096    // HWPX/4
#define NCH  16      // channels per gather thread

// Inverse map: inv[b*HWPX + pixel] = m or -1. (2 MB) Cleared via memset(0xFF).
__device__ int g_inv[BB * HWPX];

// ---------------------------------------------------------------------------
// Kernel 1: scatter entity indices. Detects int64 vs int32 location layout on
// device: under int64 (values < 128) every odd int32 word is 0; 64 consecutive
// zero odd-words under an int32 layout has probability ~(1/128)^64.
__global__ void scatter_inv_kernel(const int* __restrict__ loc32) {
    __shared__ int s_is64;
    if (threadIdx.x == 0) {
        int allzero = 1;
        #pragma unroll
        for (int k = 0; k < 64; k++) allzero &= (loc32[2 * k + 1] == 0);
        s_is64 = allzero;
    }
    __syncthreads();

    int e = blockIdx.x * blockDim.x + threadIdx.x;   // [0, B*M)
    if (e >= BB * MM) return;

    int y, x;
    if (s_is64) { y = loc32[4 * e];  x = loc32[4 * e + 2]; }
    else        { y = loc32[2 * e];  x = loc32[2 * e + 1]; }
    int b = e / MM;
    int m = e - b * MM;
    g_inv[b * HWPX + y * WPX + x] = m;
}

// ---------------------------------------------------------------------------
// Kernel 2: gather + zero-fill (R3's fastest-measured body, unchanged).
// Thread = (b, 16-channel chunk, pixel quad). All 16 entity float4s gathered
// up front (predicated LDG.128, MLP=16), then a static register transpose
// feeds 16 fully coalesced STG.128 (warp = 512B bursts). Branch-free:
// ~97% of lanes predicated off per gather, stores never diverge.
__global__ void __launch_bounds__(256) gather_out_kernel(
        const float* __restrict__ xin, float* __restrict__ out) {
    int p4 = blockIdx.x * blockDim.x + threadIdx.x;  // [0, HW4)
    int b  = blockIdx.z;
    int n0 = blockIdx.y * NCH;

    int4 inv4 = ((const int4*)g_inv)[b * HW4 + p4];

    // x[b][m][n0 + 0..15] viewed as 4 float4s; row stride NN/4 = 32 float4s.
    const float4* xb = (const float4*)(xin + (size_t)b * MM * NN) + (n0 >> 2);
    const float4  z  = make_float4(0.f, 0.f, 0.f, 0.f);

    float4 e0[4], e1[4], e2[4], e3[4];
    #pragma unroll
    for (int q = 0; q < 4; q++) {
        e0[q] = (inv4.x >= 0) ? xb[(size_t)inv4.x * (NN / 4) + q] : z;
        e1[q] = (inv4.y >= 0) ? xb[(size_t)inv4.y * (NN / 4) + q] : z;
        e2[q] = (inv4.z >= 0) ? xb[(size_t)inv4.z * (NN / 4) + q] : z;
        e3[q] = (inv4.w >= 0) ? xb[(size_t)inv4.w * (NN / 4) + q] : z;
    }

    float4* out4 = (float4*)out + ((size_t)b * NN + n0) * HW4 + p4;
    #pragma unroll
    for (int q = 0; q < 4; q++) {
        float4 a = e0[q], c = e1[q], d = e2[q], f = e3[q];
        out4[(size_t)(4 * q + 0) * HW4] = make_float4(a.x, c.x, d.x, f.x);
        out4[(size_t)(4 * q + 1) * HW4] = make_float4(a.y, c.y, d.y, f.y);
        out4[(size_t)(4 * q + 2) * HW4] = make_float4(a.z, c.z, d.z, f.z);
        out4[(size_t)(4 * q + 3) * HW4] = make_float4(a.w, c.w, d.w, f.w);
    }
}

// ---------------------------------------------------------------------------
extern "C" void kernel_launch(void* const* d_in, const int* in_sizes, int n_in,
                              void* d_out, int out_size) {
    const float* x     = (const float*)d_in[0];
    const int*   loc32 = (const int*)d_in[1];
    float*       out   = (float*)d_out;
    (void)in_sizes; (void)n_in; (void)out_size;

    // 1) inv = -1 everywhere (0xFF fill). Graph-capturable memset node. 2 MB.
    void* inv_ptr = nullptr;
    cudaGetSymbolAddress(&inv_ptr, g_inv);
    cudaMemsetAsync(inv_ptr, 0xFF, sizeof(int) * BB * HWPX, 0);

    // 2) scatter entity ids: BB*MM = 16384 threads
    scatter_inv_kernel<<<64, 256>>>(loc32);

    // 3) gather + zero-fill output: (16, 8, 32) blocks x 256 threads
    gather_out_kernel<<<dim3(HW4 / 256, NN / NCH, BB), 256>>>(x, out);
}

// round 10
// speedup vs baseline: 1.2273x; 1.2273x over previous
#include <cuda_runtime.h>
#include <stdint.h>

// Shapes (fixed):
//   x:        (B, M, N)  float32          B=32, M=512, N=128
//   location: (B, M, 2)  int64/int32 (y, x), H=W=128
//   out:      (B, N, H, W) float32
#define BB   32
#define MM   512
#define NN   128
#define WPX  128
#define HWPX 16384   // 128*128
#define HW4  4096    // HWPX/4
#define NCH  16      // channels per block
#define PPB  1024    // pixels per block (256 threads x 4)

// ---------------------------------------------------------------------------
// Single fused kernel = R6's structure (smem inverse map, one launch, zero
// prologue) + R4's Phase-B body (pipelined MLP4, 4-float4 live set, .cs
// stores) + forced 8 blocks/SM for ~100% occupancy. Across R2-R9 the two
// best WALL-CLOCK configs were exactly high-occupancy (R4, 48.9) and fused
// (R6, 49.0); this combines them.
//
// Phase A: build 2 KB smem inverse map for this block's 1024-pixel range by
//          scanning batch b's 512 locations (2 per thread, L2-resident).
//          int64-vs-int32 layout detected via __syncthreads_and on odd int32
//          words (all-zero <=> int64; under int32 these are x coords
//          ~U[0,128), P(all 256 zero) ~ 2^-1792).
// Phase B: per q: 4 predicated LDG.128 (one per entity slot), register
//          transpose, 4 streaming STG.128 (warp = 512B bursts). Only 4
//          float4s live -> fits the 32-reg budget of (256,8) = 100% occ.
__global__ void __launch_bounds__(256, 8) fused_scatter_kernel(
        const float4* __restrict__ xin,
        const int*    __restrict__ loc32,
        float4*       __restrict__ out) {
    __shared__ short s_inv[PPB];

    const int t  = threadIdx.x;
    const int b  = blockIdx.z;
    const int n0 = blockIdx.y * NCH;
    const int p0 = blockIdx.x * PPB;          // first pixel of this block

    // --- Phase A: smem inverse map ----------------------------------------
    ((int*)s_inv)[2 * t]     = -1;            // 4 shorts = -1 per thread
    ((int*)s_inv)[2 * t + 1] = -1;

    const int* locb32 = loc32 + b * MM * 2;   // int32 view of batch b
    const int* locb64 = loc32 + b * MM * 4;   // int64 view (int32 pairs)

    // layout probe (doubles as the barrier ordering smem init vs scatter):
    int is64 = __syncthreads_and(loc32[2 * t + 1] == 0);

    #pragma unroll
    for (int k = 0; k < 2; k++) {
        int e = t + 256 * k;                  // entity m in [0, 512)
        int y, x;
        if (is64) { y = locb64[4 * e]; x = locb64[4 * e + 2]; }
        else      { y = locb32[2 * e]; x = locb32[2 * e + 1]; }
        int rel = y * WPX + x - p0;
        if ((unsigned)rel < PPB) s_inv[rel] = (short)e;
    }
    __syncthreads();

    // --- Phase B: pipelined gather + zero-fill (R4 body) ------------------
    short4 iv = ((const short4*)s_inv)[t];
    int m0 = iv.x, m1 = iv.y, m2 = iv.z, m3 = iv.w;
    bool v0 = m0 >= 0, v1 = m1 >= 0, v2 = m2 >= 0, v3 = m3 >= 0;
    int i0 = m0 * (NN / 4), i1 = m1 * (NN / 4);
    int i2 = m2 * (NN / 4), i3 = m3 * (NN / 4);

    // x[b][m][n0 + 0..15] = 4 float4s at row stride NN/4 = 32.
    const float4* xb = xin + b * (MM * NN / 4) + (n0 >> 2);
    float4*       o  = out + (b * NN + n0) * HW4 + (p0 >> 2) + t;
    const float4  z  = make_float4(0.f, 0.f, 0.f, 0.f);

    #pragma unroll
    for (int q = 0; q < 4; q++) {
        float4 a = v0 ? __ldg(xb + i0 + q) : z;
        float4 c = v1 ? __ldg(xb + i1 + q) : z;
        float4 d = v2 ? __ldg(xb + i2 + q) : z;
        float4 f = v3 ? __ldg(xb + i3 + q) : z;

        __stcs(o + (4 * q + 0) * HW4, make_float4(a.x, c.x, d.x, f.x));
        __stcs(o + (4 * q + 1) * HW4, make_float4(a.y, c.y, d.y, f.y));
        __stcs(o + (4 * q + 2) * HW4, make_float4(a.z, c.z, d.z, f.z));
        __stcs(o + (4 * q + 3) * HW4, make_float4(a.w, c.w, d.w, f.w));
    }
}

// ---------------------------------------------------------------------------
extern "C" void kernel_launch(void* const* d_in, const int* in_sizes, int n_in,
                              void* d_out, int out_size) {
    const float* x     = (const float*)d_in[0];
    const int*   loc32 = (const int*)d_in[1];
    float*       out   = (float*)d_out;
    (void)in_sizes; (void)n_in; (void)out_size;

    // One launch: (16 pixel-ranges, 8 channel-chunks, 32 batches) x 256 thr.
    fused_scatter_kernel<<<dim3(HWPX / PPB, NN / NCH, BB), 256>>>(
        (const float4*)x, loc32, (float4*)out);
}